// round 14
// baseline (speedup 1.0000x reference)
#include <cuda_runtime.h>
#include <cuda_fp16.h>
typedef unsigned long long ull;
typedef unsigned int u32;

#define BN 16
#define TILE 128
#define ETH 512

__device__ float g_q[25000 * 224];
__device__ float g_k[25000 * 224];
__device__ float g_v[25000 * 224];
__device__ __half g_bthi[224 * 224];
__device__ __half g_btlo[224 * 224];
__device__ float g_wqT[7168];
__device__ float g_wkT[7168];
__device__ float g_wvT[12544];

__device__ __forceinline__ float silu_f(float x) { return x / (1.0f + __expf(-x)); }
__device__ __forceinline__ u32 sptr(const void* p) { return (u32)__cvta_generic_to_shared(p); }

__device__ __forceinline__ void ldmx4(u32& r0, u32& r1, u32& r2, u32& r3, u32 a) {
    asm volatile("ldmatrix.sync.aligned.m8n8.x4.shared.b16 {%0,%1,%2,%3},[%4];"
                 : "=r"(r0), "=r"(r1), "=r"(r2), "=r"(r3) : "r"(a));
}
__device__ __forceinline__ void mma16816(float* c, const u32* a, u32 b0, u32 b1) {
    asm volatile("mma.sync.aligned.m16n8k16.row.col.f32.f16.f16.f32 "
                 "{%0,%1,%2,%3},{%4,%5,%6,%7},{%8,%9},{%0,%1,%2,%3};"
                 : "+f"(c[0]), "+f"(c[1]), "+f"(c[2]), "+f"(c[3])
                 : "r"(a[0]), "r"(a[1]), "r"(a[2]), "r"(a[3]), "r"(b0), "r"(b1));
}
__device__ __forceinline__ void cp16(u32 d, const void* s) {
    asm volatile("cp.async.cg.shared.global [%0],[%1],16;" :: "r"(d), "l"(s));
}

__global__ void k_nop() {}

// ---------------------------------------------------------------------------
__global__ void k_prep(const float* __restrict__ W2r, const float* __restrict__ W2s,
                       const float* __restrict__ Wq, const float* __restrict__ Wk,
                       const float* __restrict__ Wv,
                       float* __restrict__ outx, float* __restrict__ outev, int N)
{
    int gid = blockIdx.x * blockDim.x + threadIdx.x, st = gridDim.x * blockDim.x;
    int nx = N * 224, nz = N * 239;
    for (int i = gid; i < nz; i += st) { if (i < nx) outx[i] = 0.f; else outev[i - nx] = 0.f; }
    for (int t = gid; t < 224 * 224; t += st) {
        int n = t / 224, k = t - n * 224;
        float val = (k < 112) ? W2r[k * 224 + n] : W2s[(k - 112) * 224 + n];
        __half h = __float2half_rn(val);
        g_bthi[t] = h;
        g_btlo[t] = __float2half_rn(val - __half2float(h));
    }
    for (int i = gid; i < 7168; i += st) {
        int h = i >> 10, rem = i & 1023, jj = rem >> 5, ic = rem & 31;
        g_wqT[i] = Wq[h * 1024 + ic * 32 + jj];
        g_wkT[i] = Wk[h * 1024 + ic * 32 + jj];
    }
    for (int i = gid; i < 12544; i += st) {
        int h = i / 3136, rem = i - h * 3136, jj = rem / 56, ic = rem - jj * 56;
        g_wvT[i] = Wv[h * 3136 + ic * 56 + jj];
    }
}

// ---------------------------------------------------------------------------
__global__ void __launch_bounds__(256, 3) k_node(const float* __restrict__ x, int N)
{
    __shared__ float xs[BN * 224];
    int tid = threadIdx.x, nb0 = blockIdx.x * BN;
    int cnt = N - nb0; if (cnt > BN) cnt = BN; if (cnt < 0) cnt = 0;
    for (int idx = tid; idx < BN * 224; idx += 256) {
        int u = idx / 224, f = idx - u * 224;
        xs[idx] = (u < cnt) ? x[(nb0 + u) * 224 + f] : 0.f;
    }
    __syncthreads();
    if (tid < 224) {
        int h = tid >> 5, iq = tid & 31, hv = tid / 56, iv = tid - hv * 56;
        float aq[BN], ak[BN], av[BN];
#pragma unroll
        for (int u = 0; u < BN; u++) { aq[u] = ak[u] = av[u] = 0.f; }
#pragma unroll 4
        for (int j = 0; j < 32; j++) {
            float wq = g_wqT[h * 1024 + j * 32 + iq], wk = g_wkT[h * 1024 + j * 32 + iq];
#pragma unroll
            for (int u = 0; u < BN; u++) {
                float xv = xs[u * 224 + h * 32 + j];
                aq[u] += wq * xv; ak[u] += wk * xv;
            }
        }
#pragma unroll 4
        for (int j = 0; j < 56; j++) {
            float wv = g_wvT[hv * 3136 + j * 56 + iv];
#pragma unroll
            for (int u = 0; u < BN; u++) av[u] += wv * xs[u * 224 + hv * 56 + j];
        }
        for (int u = 0; u < cnt; u++) {
            g_q[(nb0 + u) * 224 + tid] = silu_f(aq[u]);
            g_k[(nb0 + u) * 224 + tid] = silu_f(ak[u]);
            g_v[(nb0 + u) * 224 + tid] = av[u];
        }
    }
}

// ---------------------------------------------------------------------------
// smem: ACT_HI [0,59392)B, ACT_LO [59392,118784)B (fp16, stride 232 halves).
// After phase B the ACT region is reused as qk[e][c] fp32, stride 228.
// Float scratch from 118784B; B double buffer at BB_B.
#define AH_B   0
#define AL_B   59392
#define RBF_F  29696
#define TMP_F  33792
#define L0_F   35712
#define ALPH_F 36096
#define CUT_F  36992
#define SI_F   37120
#define SJ_F   37248
#define B2_F   37376
#define BB_B   150400
#define ESM_BYTES (150400 + 28672)

__device__ __forceinline__ void issue_chunk(u32 bBase, int buf, int ks, int tid) {
    u32 dst0 = bBase + (u32)(buf * 14336);
    for (int idx = tid; idx < 896; idx += ETH) {
        int half = idx / 448, i = idx - half * 448;
        int n = i >> 1, s = i & 1;
        const __half* src = (half ? g_btlo : g_bthi) + n * 224 + ks * 16 + s * 8;
        cp16(dst0 + (u32)(half * 7168 + n * 32 + s * 16), src);
    }
}

__global__ void __launch_bounds__(ETH) k_edge(
    const float* __restrict__ ev, const float* __restrict__ rbf,
    const float* __restrict__ ylm, const float* __restrict__ cut,
    const int* __restrict__ idx_i, const int* __restrict__ idx_j,
    const float* __restrict__ W1r, const float* __restrict__ b1r,
    const float* __restrict__ b2r,
    const float* __restrict__ W1s, const float* __restrict__ b1s,
    const float* __restrict__ b2s,
    float* __restrict__ outx, float* __restrict__ outev, int P)
{
    extern __shared__ float sm[];
    __half* ah = (__half*)((char*)sm + AH_B);
    __half* al = (__half*)((char*)sm + AL_B);
    float* qk = sm;                       // reuses ACT region after phase B
    int* sI = (int*)(sm + SI_F); int* sJ = (int*)(sm + SJ_F);

    int tid = threadIdx.x, lane = tid & 31, wid = tid >> 5;
    int p0 = blockIdx.x * TILE;
    int vend = P - p0; if (vend > TILE) vend = TILE;
    u32 bBase = sptr((char*)sm + BB_B);

    issue_chunk(bBase, 0, 0, tid);
    asm volatile("cp.async.commit_group;");

    for (int idx = tid; idx < TILE; idx += ETH) {
        int p = p0 + idx; bool v = p < P;
        sI[idx] = v ? idx_i[p] : 0;
        sJ[idx] = v ? idx_j[p] : 0;
        sm[CUT_F + idx] = v ? cut[p] : 0.f;
    }
    for (int idx = tid; idx < 224; idx += ETH) sm[B2_F + idx] = b2r[idx] + b2s[idx];
    for (int idx = tid; idx < TILE * 7; idx += ETH) sm[ALPH_F + idx] = 0.f;
    __syncthreads();
    for (int idx = tid; idx < TILE * 32; idx += ETH) {
        int e = idx >> 5, j = idx & 31; int p = p0 + e;
        sm[RBF_F + idx] = (p < P) ? rbf[p * 32 + j] * sm[CUT_F + e] : 0.f;
    }
    for (int idx = tid; idx < TILE * 15; idx += ETH) {
        int e = idx / 15, o = idx - e * 15; int p = p0 + e;
        float d = 0.f;
        if (p < P) d = ev[sJ[e] * 15 + o] - ev[sI[e] * 15 + o];
        sm[TMP_F + idx] = d * d;
    }
    __syncthreads();
    for (int idx = tid; idx < TILE * 3; idx += ETH) {
        int e = idx / 3, dg = idx - e * 3;
        int o0 = (dg == 0) ? 0 : ((dg == 1) ? 3 : 8);
        int o1 = (dg == 0) ? 3 : ((dg == 1) ? 8 : 15);
        float s = 0.f;
        for (int o = o0; o < o1; o++) s += sm[TMP_F + e * 15 + o];
        sm[L0_F + idx] = s;
    }
    __syncthreads();

    // Phase A: t<448: a = t>>1, edge-half = t&1 (64 edges each)
    if (tid < 448) {
        int a = tid >> 1, ebase = (tid & 1) * 64;
        bool isr = (a < 112);
        float b0 = isr ? b1r[a] : b1s[a - 112];
        float ws0 = 0, ws1 = 0, ws2 = 0;
        if (!isr) { ws0 = W1s[a - 112]; ws1 = W1s[a]; ws2 = W1s[a + 112]; }
        for (int ch = 0; ch < 4; ch++) {
            float acc[16];
#pragma unroll
            for (int e = 0; e < 16; e++) acc[e] = b0;
            if (isr) {
#pragma unroll
                for (int j4 = 0; j4 < 8; j4++) {
                    float w0 = W1r[(j4 * 4 + 0) * 112 + a];
                    float w1 = W1r[(j4 * 4 + 1) * 112 + a];
                    float w2 = W1r[(j4 * 4 + 2) * 112 + a];
                    float w3 = W1r[(j4 * 4 + 3) * 112 + a];
#pragma unroll
                    for (int e = 0; e < 16; e++) {
                        float4 r4 = *(const float4*)&sm[RBF_F + (ebase + ch * 16 + e) * 32 + j4 * 4];
                        acc[e] += r4.x * w0 + r4.y * w1 + r4.z * w2 + r4.w * w3;
                    }
                }
            } else {
#pragma unroll
                for (int e = 0; e < 16; e++) {
                    int ee = ebase + ch * 16 + e;
                    acc[e] += sm[L0_F + ee * 3] * ws0 + sm[L0_F + ee * 3 + 1] * ws1 + sm[L0_F + ee * 3 + 2] * ws2;
                }
            }
#pragma unroll
            for (int e = 0; e < 16; e++) {
                int ee = ebase + ch * 16 + e;
                float v = silu_f(acc[e]);
                __half h = __float2half_rn(v);
                ah[ee * 232 + a] = h;
                al[ee * 232 + a] = __float2half_rn(v - __half2float(h));
            }
        }
    }
    __syncthreads();

    // Phase B: 16 warps = 8 m-tiles x 2 n-halves; hi/lo 3-pass fp16 mma
    int mb = (wid & 7) * 16;
    int h2 = wid >> 3;
    int nb = h2 * 112;
    float acc[56];
#pragma unroll
    for (int i = 0; i < 56; i++) acc[i] = 0.f;

    u32 aAddrH = sptr(ah) + (u32)((((mb + (lane & 15)) * 232 + (lane >> 4) * 8)) * 2);
    u32 aAddrL = aAddrH + (u32)AL_B;
    int l8 = lane & 7, selk = (lane >> 3) & 1, seln = (lane >> 4) & 1;
    u32 bFragOff = (u32)((h2 * 112 + seln * 8 + l8) * 32 + selk * 16);

    for (int ks = 0; ks < 14; ks++) {
        if (ks > 0) __syncthreads();
        if (ks < 13) issue_chunk(bBase, (ks + 1) & 1, ks + 1, tid);
        asm volatile("cp.async.commit_group;");
        asm volatile("cp.async.wait_group 1;");
        __syncthreads();

        u32 aH[4], aL[4];
        ldmx4(aH[0], aH[1], aH[2], aH[3], aAddrH + (u32)(ks * 32));
        ldmx4(aL[0], aL[1], aL[2], aL[3], aAddrL + (u32)(ks * 32));
        u32 bh_base = bBase + (u32)((ks & 1) * 14336) + bFragOff;
        u32 bl_base = bh_base + 7168u;
#pragma unroll
        for (int t = 0; t < 7; t++) {
            u32 bh0, bh1, bh2, bh3, bl0, bl1, bl2, bl3;
            ldmx4(bh0, bh1, bh2, bh3, bh_base + (u32)(t * 512));
            ldmx4(bl0, bl1, bl2, bl3, bl_base + (u32)(t * 512));
            float* c0 = &acc[(t * 2 + 0) * 4];
            float* c1 = &acc[(t * 2 + 1) * 4];
            mma16816(c0, aH, bh0, bh1);
            mma16816(c1, aH, bh2, bh3);
            mma16816(c0, aH, bl0, bl1);
            mma16816(c1, aH, bl2, bl3);
            mma16816(c0, aL, bh0, bh1);
            mma16816(c1, aL, bh2, bh3);
        }
    }
    __syncthreads();   // all A reads done; ACT region now reusable

    // Stage qk[e][c] = q_i[c]*k_j[c] (coalesced row reads), stride 228
    for (int idx = tid; idx < TILE * 224; idx += ETH) {
        int e = idx / 224, c = idx - e * 224;
        qk[e * 228 + c] = g_q[(size_t)sI[e] * 224 + c] * g_k[(size_t)sJ[e] * 224 + c];
    }
    __syncthreads();

    // Fused epilogue from MMA fragments + smem qk
    {
        int r0 = mb + (lane >> 2);
        int e0 = r0, e1 = r0 + 8;
        int ncol0 = nb + 2 * (lane & 3);
        float s0[4] = {0.f, 0.f, 0.f, 0.f}, s1[4] = {0.f, 0.f, 0.f, 0.f};
#pragma unroll
        for (int nt = 0; nt < 14; nt++) {
            int n = ncol0 + nt * 8;
            int gs = (h2 == 0) ? (nt >> 2) : ((nt + 2) >> 2);
            float2 b2v = *(float2*)&sm[B2_F + n];
            float2 qa = *(float2*)&qk[e0 * 228 + n];
            float2 qb = *(float2*)&qk[e1 * 228 + n];
            s0[gs] += (acc[nt * 4 + 0] + b2v.x) * qa.x + (acc[nt * 4 + 1] + b2v.y) * qa.y;
            s1[gs] += (acc[nt * 4 + 2] + b2v.x) * qb.x + (acc[nt * 4 + 3] + b2v.y) * qb.y;
        }
#pragma unroll
        for (int off = 1; off <= 2; off <<= 1) {
#pragma unroll
            for (int s = 0; s < 4; s++) {
                s0[s] += __shfl_xor_sync(0xffffffffu, s0[s], off);
                s1[s] += __shfl_xor_sync(0xffffffffu, s1[s], off);
            }
        }
        if ((lane & 3) == 0) {
#pragma unroll
            for (int s = 0; s < 4; s++) {
                int g = s + 3 * h2;
                atomicAdd(&sm[ALPH_F + e0 * 7 + g], s0[s]);
                atomicAdd(&sm[ALPH_F + e1 * 7 + g], s1[s]);
            }
        }
    }
    __syncthreads();

    // Phase C: segment scatter (idx_i sorted); cut folded here
    if (tid < 224) {
        int h = tid / 56;
        int cur = sI[0]; float a2 = 0.f;
#pragma unroll 4
        for (int e = 0; e < vend; e++) {
            int i = sI[e];
            if (i != cur) { atomicAdd(&outx[cur * 224 + tid], a2); a2 = 0.f; cur = i; }
            a2 += sm[ALPH_F + e * 7 + h] * sm[CUT_F + e] * g_v[(size_t)sJ[e] * 224 + tid];
        }
        atomicAdd(&outx[cur * 224 + tid], a2);
    } else if (tid < 239) {
        int o = tid - 224;
        int dh = (o < 3) ? 4 : ((o < 8) ? 5 : 6);
        int cur = sI[0]; float a2 = 0.f;
#pragma unroll 4
        for (int e = 0; e < vend; e++) {
            int i = sI[e];
            if (i != cur) { atomicAdd(&outev[cur * 15 + o], a2); a2 = 0.f; cur = i; }
            a2 += sm[ALPH_F + e * 7 + dh] * sm[CUT_F + e] * ylm[(size_t)(p0 + e) * 15 + o];
        }
        atomicAdd(&outev[cur * 15 + o], a2);
    }
}

// ---------------------------------------------------------------------------
extern "C" void kernel_launch(void* const* d_in, const int* in_sizes, int n_in,
                              void* d_out, int out_size) {
    const float* x = (const float*)d_in[0];
    const float* ev = (const float*)d_in[1];
    const float* rbf = (const float*)d_in[2];
    const float* ylm = (const float*)d_in[3];
    const float* cut = (const float*)d_in[4];
    const int* idx_i = (const int*)d_in[5];
    const int* idx_j = (const int*)d_in[6];
    const float* W1r = (const float*)d_in[7];
    const float* b1r = (const float*)d_in[8];
    const float* W2r = (const float*)d_in[9];
    const float* b2r = (const float*)d_in[10];
    const float* W1s = (const float*)d_in[11];
    const float* b1s = (const float*)d_in[12];
    const float* W2s = (const float*)d_in[13];
    const float* b2s = (const float*)d_in[14];
    const float* Wq = (const float*)d_in[15];
    const float* Wk = (const float*)d_in[16];
    const float* Wv = (const float*)d_in[17];

    int N = in_sizes[0] / 224;
    int P = in_sizes[4];
    float* outx = (float*)d_out;
    float* outev = outx + (size_t)N * 224;

    cudaFuncSetAttribute(k_edge, cudaFuncAttributeMaxDynamicSharedMemorySize, ESM_BYTES);
    k_nop<<<1, 32>>>();
    k_prep<<<512, 256>>>(W2r, W2s, Wq, Wk, Wv, outx, outev, N);
    k_node<<<(N + BN - 1) / BN, 256>>>(x, N);
    k_edge<<<(P + TILE - 1) / TILE, ETH, ESM_BYTES>>>(
        ev, rbf, ylm, cut, idx_i, idx_j, W1r, b1r, b2r, W1s, b1s, b2s, outx, outev, P);
}

// round 15
// speedup vs baseline: 1.2726x; 1.2726x over previous
#include <cuda_runtime.h>
#include <cuda_fp16.h>
typedef unsigned long long ull;
typedef unsigned int u32;

#define BN 16
#define TILE 64

__device__ float g_q[25000 * 224];
__device__ float g_k[25000 * 224];
__device__ float g_v[25000 * 224];
__device__ __half g_bthi[224 * 224];
__device__ __half g_btlo[224 * 224];
__device__ float g_wqT[7168];
__device__ float g_wkT[7168];
__device__ float g_wvT[12544];

__device__ __forceinline__ float silu_f(float x) { return x / (1.0f + __expf(-x)); }
__device__ __forceinline__ u32 sptr(const void* p) { return (u32)__cvta_generic_to_shared(p); }

__device__ __forceinline__ void ldmx4(u32& r0, u32& r1, u32& r2, u32& r3, u32 a) {
    asm volatile("ldmatrix.sync.aligned.m8n8.x4.shared.b16 {%0,%1,%2,%3},[%4];"
                 : "=r"(r0), "=r"(r1), "=r"(r2), "=r"(r3) : "r"(a));
}
__device__ __forceinline__ void mma16816(float* c, const u32* a, u32 b0, u32 b1) {
    asm volatile("mma.sync.aligned.m16n8k16.row.col.f32.f16.f16.f32 "
                 "{%0,%1,%2,%3},{%4,%5,%6,%7},{%8,%9},{%0,%1,%2,%3};"
                 : "+f"(c[0]), "+f"(c[1]), "+f"(c[2]), "+f"(c[3])
                 : "r"(a[0]), "r"(a[1]), "r"(a[2]), "r"(a[3]), "r"(b0), "r"(b1));
}
__device__ __forceinline__ void cp16(u32 d, const void* s) {
    asm volatile("cp.async.cg.shared.global [%0],[%1],16;" :: "r"(d), "l"(s));
}

__global__ void k_nop() {}

// ---------------------------------------------------------------------------
__global__ void k_prep(const float* __restrict__ W2r, const float* __restrict__ W2s,
                       const float* __restrict__ Wq, const float* __restrict__ Wk,
                       const float* __restrict__ Wv,
                       float* __restrict__ outx, float* __restrict__ outev, int N)
{
    int gid = blockIdx.x * blockDim.x + threadIdx.x, st = gridDim.x * blockDim.x;
    int nx = N * 224, nz = N * 239;
    for (int i = gid; i < nz; i += st) { if (i < nx) outx[i] = 0.f; else outev[i - nx] = 0.f; }
    for (int t = gid; t < 224 * 224; t += st) {
        int n = t / 224, k = t - n * 224;
        float val = (k < 112) ? W2r[k * 224 + n] : W2s[(k - 112) * 224 + n];
        __half h = __float2half_rn(val);
        g_bthi[t] = h;
        g_btlo[t] = __float2half_rn(val - __half2float(h));
    }
    for (int i = gid; i < 7168; i += st) {
        int h = i >> 10, rem = i & 1023, jj = rem >> 5, ic = rem & 31;
        g_wqT[i] = Wq[h * 1024 + ic * 32 + jj];
        g_wkT[i] = Wk[h * 1024 + ic * 32 + jj];
    }
    for (int i = gid; i < 12544; i += st) {
        int h = i / 3136, rem = i - h * 3136, jj = rem / 56, ic = rem - jj * 56;
        g_wvT[i] = Wv[h * 3136 + ic * 56 + jj];
    }
}

// ---------------------------------------------------------------------------
__global__ void __launch_bounds__(256, 3) k_node(const float* __restrict__ x, int N)
{
    __shared__ float xs[BN * 224];
    int tid = threadIdx.x, nb0 = blockIdx.x * BN;
    int cnt = N - nb0; if (cnt > BN) cnt = BN; if (cnt < 0) cnt = 0;
    for (int idx = tid; idx < BN * 224; idx += 256) {
        int u = idx / 224, f = idx - u * 224;
        xs[idx] = (u < cnt) ? x[(nb0 + u) * 224 + f] : 0.f;
    }
    __syncthreads();
    if (tid < 224) {
        int h = tid >> 5, iq = tid & 31, hv = tid / 56, iv = tid - hv * 56;
        float aq[BN], ak[BN], av[BN];
#pragma unroll
        for (int u = 0; u < BN; u++) { aq[u] = ak[u] = av[u] = 0.f; }
#pragma unroll 4
        for (int j = 0; j < 32; j++) {
            float wq = g_wqT[h * 1024 + j * 32 + iq], wk = g_wkT[h * 1024 + j * 32 + iq];
#pragma unroll
            for (int u = 0; u < BN; u++) {
                float xv = xs[u * 224 + h * 32 + j];
                aq[u] += wq * xv; ak[u] += wk * xv;
            }
        }
#pragma unroll 4
        for (int j = 0; j < 56; j++) {
            float wv = g_wvT[hv * 3136 + j * 56 + iv];
#pragma unroll
            for (int u = 0; u < BN; u++) av[u] += wv * xs[u * 224 + hv * 56 + j];
        }
        for (int u = 0; u < cnt; u++) {
            g_q[(nb0 + u) * 224 + tid] = silu_f(aq[u]);
            g_k[(nb0 + u) * 224 + tid] = silu_f(ak[u]);
            g_v[(nb0 + u) * 224 + tid] = av[u];
        }
    }
}

// ---------------------------------------------------------------------------
// smem: ACT_HI [0,29696)B, ACT_LO [29696,59392)B fp16 stride 232.
// After phase B, [0,58368)B reused as qk[e][c] fp32 stride 228.
// Float scratch from 59392B; B double buffer at BB_B.
#define AH_B   0
#define AL_B   29696
#define RBF_F  14848
#define TMP_F  16896
#define L0_F   17856
#define ALPH_F 18048
#define CUT_F  18496
#define SI_F   18560
#define SJ_F   18624
#define B2_F   18688
#define BB_B   75648            // 2 stages x (7168 hi + 7168 lo) = 28672 B
#define ESM_BYTES (75648 + 28672)

__device__ __forceinline__ void issue_chunk(u32 bBase, int buf, int ks, int tid) {
    u32 dst0 = bBase + (u32)(buf * 14336);
    for (int idx = tid; idx < 896; idx += 256) {
        int half = idx / 448, i = idx - half * 448;
        int n = i >> 1, s = i & 1;
        const __half* src = (half ? g_btlo : g_bthi) + n * 224 + ks * 16 + s * 8;
        cp16(dst0 + (u32)(half * 7168 + n * 32 + s * 16), src);
    }
}

__global__ void __launch_bounds__(256, 2) k_edge(
    const float* __restrict__ ev, const float* __restrict__ rbf,
    const float* __restrict__ ylm, const float* __restrict__ cut,
    const int* __restrict__ idx_i, const int* __restrict__ idx_j,
    const float* __restrict__ W1r, const float* __restrict__ b1r,
    const float* __restrict__ b2r,
    const float* __restrict__ W1s, const float* __restrict__ b1s,
    const float* __restrict__ b2s,
    float* __restrict__ outx, float* __restrict__ outev, int P)
{
    extern __shared__ float sm[];
    __half* ah = (__half*)((char*)sm + AH_B);
    __half* al = (__half*)((char*)sm + AL_B);
    float* qk = sm;                        // reuses ACT region after phase B
    int* sI = (int*)(sm + SI_F); int* sJ = (int*)(sm + SJ_F);

    int tid = threadIdx.x, lane = tid & 31, wid = tid >> 5;
    int p0 = blockIdx.x * TILE;
    int vend = P - p0; if (vend > TILE) vend = TILE;
    u32 bBase = sptr((char*)sm + BB_B);

    issue_chunk(bBase, 0, 0, tid);
    asm volatile("cp.async.commit_group;");

    for (int idx = tid; idx < TILE; idx += 256) {
        int p = p0 + idx; bool v = p < P;
        sI[idx] = v ? idx_i[p] : 0;
        sJ[idx] = v ? idx_j[p] : 0;
        sm[CUT_F + idx] = v ? cut[p] : 0.f;
    }
    for (int idx = tid; idx < 224; idx += 256) sm[B2_F + idx] = b2r[idx] + b2s[idx];
    for (int idx = tid; idx < 448; idx += 256) sm[ALPH_F + idx] = 0.f;
    __syncthreads();
    for (int idx = tid; idx < TILE * 32; idx += 256) {
        int e = idx >> 5, j = idx & 31; int p = p0 + e;
        sm[RBF_F + idx] = (p < P) ? rbf[p * 32 + j] * sm[CUT_F + e] : 0.f;
    }
    for (int idx = tid; idx < TILE * 15; idx += 256) {
        int e = idx / 15, o = idx - e * 15; int p = p0 + e;
        float d = 0.f;
        if (p < P) d = ev[sJ[e] * 15 + o] - ev[sI[e] * 15 + o];
        sm[TMP_F + idx] = d * d;
    }
    __syncthreads();
    for (int idx = tid; idx < TILE * 3; idx += 256) {
        int e = idx / 3, dg = idx - e * 3;
        int o0 = (dg == 0) ? 0 : ((dg == 1) ? 3 : 8);
        int o1 = (dg == 0) ? 3 : ((dg == 1) ? 8 : 15);
        float s = 0.f;
        for (int o = o0; o < o1; o++) s += sm[TMP_F + e * 15 + o];
        sm[L0_F + idx] = s;
    }
    __syncthreads();

    // Phase A: hidden acts -> fp16 hi/lo [edge][chan], stride 232 halves
    if (tid < 224) {
        int a = tid;
        bool isr = (a < 112);
        float b0 = isr ? b1r[a] : b1s[a - 112];
        float ws0 = 0, ws1 = 0, ws2 = 0;
        if (!isr) { ws0 = W1s[a - 112]; ws1 = W1s[a]; ws2 = W1s[a + 112]; }
        for (int ch = 0; ch < 4; ch++) {
            float acc[16];
#pragma unroll
            for (int e = 0; e < 16; e++) acc[e] = b0;
            if (isr) {
#pragma unroll
                for (int j4 = 0; j4 < 8; j4++) {
                    float w0 = W1r[(j4 * 4 + 0) * 112 + a];
                    float w1 = W1r[(j4 * 4 + 1) * 112 + a];
                    float w2 = W1r[(j4 * 4 + 2) * 112 + a];
                    float w3 = W1r[(j4 * 4 + 3) * 112 + a];
#pragma unroll
                    for (int e = 0; e < 16; e++) {
                        float4 r4 = *(const float4*)&sm[RBF_F + (ch * 16 + e) * 32 + j4 * 4];
                        acc[e] += r4.x * w0 + r4.y * w1 + r4.z * w2 + r4.w * w3;
                    }
                }
            } else {
#pragma unroll
                for (int e = 0; e < 16; e++) {
                    int ee = ch * 16 + e;
                    acc[e] += sm[L0_F + ee * 3] * ws0 + sm[L0_F + ee * 3 + 1] * ws1 + sm[L0_F + ee * 3 + 2] * ws2;
                }
            }
#pragma unroll
            for (int e = 0; e < 16; e++) {
                int ee = ch * 16 + e;
                float v = silu_f(acc[e]);
                __half h = __float2half_rn(v);
                ah[ee * 232 + a] = h;
                al[ee * 232 + a] = __float2half_rn(v - __half2float(h));
            }
        }
    }
    __syncthreads();

    // Phase B: hi/lo fp16 mma.sync, B staged in smem (double buffer)
    int mb = (wid & 3) * 16;
    int h2 = wid >> 2;
    int nb = h2 * 112;
    float acc[56];
#pragma unroll
    for (int i = 0; i < 56; i++) acc[i] = 0.f;

    u32 aAddrH = sptr(ah) + (u32)((((mb + (lane & 15)) * 232 + (lane >> 4) * 8)) * 2);
    u32 aAddrL = aAddrH + (u32)AL_B;
    int l8 = lane & 7, selk = (lane >> 3) & 1, seln = (lane >> 4) & 1;
    u32 bFragOff = (u32)((h2 * 112 + seln * 8 + l8) * 32 + selk * 16);

    for (int ks = 0; ks < 14; ks++) {
        if (ks > 0) __syncthreads();
        if (ks < 13) issue_chunk(bBase, (ks + 1) & 1, ks + 1, tid);
        asm volatile("cp.async.commit_group;");
        asm volatile("cp.async.wait_group 1;");
        __syncthreads();

        u32 aH[4], aL[4];
        ldmx4(aH[0], aH[1], aH[2], aH[3], aAddrH + (u32)(ks * 32));
        ldmx4(aL[0], aL[1], aL[2], aL[3], aAddrL + (u32)(ks * 32));
        u32 bh_base = bBase + (u32)((ks & 1) * 14336) + bFragOff;
        u32 bl_base = bh_base + 7168u;
#pragma unroll
        for (int t = 0; t < 7; t++) {
            u32 bh0, bh1, bh2, bh3, bl0, bl1, bl2, bl3;
            ldmx4(bh0, bh1, bh2, bh3, bh_base + (u32)(t * 512));
            ldmx4(bl0, bl1, bl2, bl3, bl_base + (u32)(t * 512));
            float* c0 = &acc[(t * 2 + 0) * 4];
            float* c1 = &acc[(t * 2 + 1) * 4];
            mma16816(c0, aH, bh0, bh1);
            mma16816(c1, aH, bh2, bh3);
            mma16816(c0, aH, bl0, bl1);
            mma16816(c1, aH, bl2, bl3);
            mma16816(c0, aL, bh0, bh1);
            mma16816(c1, aL, bh2, bh3);
        }
    }
    __syncthreads();   // all A reads done; ACT region reusable

    // Stage qk[e][c] = q_i[c]*k_j[c] with coalesced row reads, stride 228
    for (int idx = tid; idx < TILE * 224; idx += 256) {
        int e = idx >> 8; int c = idx & 255;   // 256-wide split: c<224 valid
        e = idx / 224; c = idx - e * 224;
        qk[e * 228 + c] = g_q[(size_t)sI[e] * 224 + c] * g_k[(size_t)sJ[e] * 224 + c];
    }
    __syncthreads();

    // Fused epilogue from MMA fragments + smem qk
    {
        int r0 = mb + (lane >> 2);
        int e0 = r0, e1 = r0 + 8;
        int ncol0 = nb + 2 * (lane & 3);
        float s0[4] = {0.f, 0.f, 0.f, 0.f}, s1[4] = {0.f, 0.f, 0.f, 0.f};
#pragma unroll
        for (int nt = 0; nt < 14; nt++) {
            int n = ncol0 + nt * 8;
            int gs = (h2 == 0) ? (nt >> 2) : ((nt + 2) >> 2);
            float2 b2v = *(float2*)&sm[B2_F + n];
            float2 qa = *(float2*)&qk[e0 * 228 + n];
            float2 qb = *(float2*)&qk[e1 * 228 + n];
            s0[gs] += (acc[nt * 4 + 0] + b2v.x) * qa.x + (acc[nt * 4 + 1] + b2v.y) * qa.y;
            s1[gs] += (acc[nt * 4 + 2] + b2v.x) * qb.x + (acc[nt * 4 + 3] + b2v.y) * qb.y;
        }
#pragma unroll
        for (int off = 1; off <= 2; off <<= 1) {
#pragma unroll
            for (int s = 0; s < 4; s++) {
                s0[s] += __shfl_xor_sync(0xffffffffu, s0[s], off);
                s1[s] += __shfl_xor_sync(0xffffffffu, s1[s], off);
            }
        }
        if ((lane & 3) == 0) {
#pragma unroll
            for (int s = 0; s < 4; s++) {
                int g = s + 3 * h2;
                atomicAdd(&sm[ALPH_F + e0 * 7 + g], s0[s]);
                atomicAdd(&sm[ALPH_F + e1 * 7 + g], s1[s]);
            }
        }
    }
    __syncthreads();

    // Phase C: segment scatter (idx_i sorted); cut folded here
    if (tid < 224) {
        int h = tid / 56;
        int cur = sI[0]; float a2 = 0.f;
#pragma unroll 4
        for (int e = 0; e < vend; e++) {
            int i = sI[e];
            if (i != cur) { atomicAdd(&outx[cur * 224 + tid], a2); a2 = 0.f; cur = i; }
            a2 += sm[ALPH_F + e * 7 + h] * sm[CUT_F + e] * g_v[(size_t)sJ[e] * 224 + tid];
        }
        atomicAdd(&outx[cur * 224 + tid], a2);
    } else if (tid < 239) {
        int o = tid - 224;
        int dh = (o < 3) ? 4 : ((o < 8) ? 5 : 6);
        int cur = sI[0]; float a2 = 0.f;
#pragma unroll 4
        for (int e = 0; e < vend; e++) {
            int i = sI[e];
            if (i != cur) { atomicAdd(&outev[cur * 15 + o], a2); a2 = 0.f; cur = i; }
            a2 += sm[ALPH_F + e * 7 + dh] * sm[CUT_F + e] * ylm[(size_t)(p0 + e) * 15 + o];
        }
        atomicAdd(&outev[cur * 15 + o], a2);
    }
}

// ---------------------------------------------------------------------------
extern "C" void kernel_launch(void* const* d_in, const int* in_sizes, int n_in,
                              void* d_out, int out_size) {
    const float* x = (const float*)d_in[0];
    const float* ev = (const float*)d_in[1];
    const float* rbf = (const float*)d_in[2];
    const float* ylm = (const float*)d_in[3];
    const float* cut = (const float*)d_in[4];
    const int* idx_i = (const int*)d_in[5];
    const int* idx_j = (const int*)d_in[6];
    const float* W1r = (const float*)d_in[7];
    const float* b1r = (const float*)d_in[8];
    const float* W2r = (const float*)d_in[9];
    const float* b2r = (const float*)d_in[10];
    const float* W1s = (const float*)d_in[11];
    const float* b1s = (const float*)d_in[12];
    const float* W2s = (const float*)d_in[13];
    const float* b2s = (const float*)d_in[14];
    const float* Wq = (const float*)d_in[15];
    const float* Wk = (const float*)d_in[16];
    const float* Wv = (const float*)d_in[17];

    int N = in_sizes[0] / 224;
    int P = in_sizes[4];
    float* outx = (float*)d_out;
    float* outev = outx + (size_t)N * 224;

    cudaFuncSetAttribute(k_edge, cudaFuncAttributeMaxDynamicSharedMemorySize, ESM_BYTES);
    k_nop<<<1, 32>>>();
    k_prep<<<512, 256>>>(W2r, W2s, Wq, Wk, Wv, outx, outev, N);
    k_node<<<(N + BN - 1) / BN, 256>>>(x, N);
    k_edge<<<(P + TILE - 1) / TILE, 256, ESM_BYTES>>>(
        ev, rbf, ylm, cut, idx_i, idx_j, W1r, b1r, b2r, W1s, b1s, b2s, outx, outev, P);
}